// round 3
// baseline (speedup 1.0000x reference)
#include <cuda_runtime.h>

#define BH   32      // B*H
#define SEQ  2048
#define DH   128
#define BM   128     // q rows per CTA
#define TK   64      // k/v rows per tile
#define QPAD 132     // padded row stride for Qs/Ks/Vs (floats)
#define SPAD 68      // padded row stride for Ss (floats)

typedef unsigned int u32;

__device__ __forceinline__ float to_tf32(float x) {
    u32 u;
    asm("cvt.rna.tf32.f32 %0, %1;" : "=r"(u) : "f"(x));
    return __uint_as_float(u);
}

__device__ __forceinline__ void mma8(float* c,
                                     u32 a0, u32 a1, u32 a2, u32 a3,
                                     u32 b0, u32 b1) {
    asm volatile(
        "mma.sync.aligned.m16n8k8.row.col.f32.tf32.tf32.f32 "
        "{%0,%1,%2,%3},{%4,%5,%6,%7},{%8,%9},{%0,%1,%2,%3};\n"
        : "+f"(c[0]), "+f"(c[1]), "+f"(c[2]), "+f"(c[3])
        : "r"(a0), "r"(a1), "r"(a2), "r"(a3), "r"(b0), "r"(b1));
}

// O = relu(Q K^T * scale)^2 @ V, fused, no softmax.
// CTA: 256 threads (8 warps). Warp grid: 2 (m) x 4 (n).
//   GEMM1: S[128 x 64] = Q[128 x 128] @ K^T.  warp tile 64 x 16.
//   GEMM2: O[128 x 128] += S[128 x 64] @ V[64 x 128]. warp tile 64 x 32.
__global__ void __launch_bounds__(256, 1)
attn_relu2_kernel(const float* __restrict__ q, const float* __restrict__ k,
                  const float* __restrict__ v, const float* __restrict__ scale_p,
                  float* __restrict__ out) {
    extern __shared__ float smem[];
    float* Qs = smem;                         // [BM][QPAD]
    float* Ks = Qs + BM * QPAD;               // [TK][QPAD]
    float* Vs = Ks + TK * QPAD;               // [TK][QPAD]
    float* Ss = Vs + TK * QPAD;               // [BM][SPAD]

    const int bh = blockIdx.y;
    const int q0 = blockIdx.x * BM;
    const float scale = *scale_p;
    const size_t base = (size_t)bh * SEQ * DH;

    const int tid  = threadIdx.x;
    const int lane = tid & 31;
    const int warp = tid >> 5;
    const int g = lane >> 2;   // group id (0..7)
    const int t = lane & 3;    // thread-in-group (0..3)
    const int wm = warp & 1;   // m split (0..1)
    const int wn = warp >> 1;  // n split (0..3)

    // ---- load Q tile [BM x DH] into SMEM, converted to tf32 ----
    {
        const float4* qg = (const float4*)(q + base + (size_t)q0 * DH);
        #pragma unroll
        for (int i = 0; i < 16; i++) {
            int idx = tid + i * 256;          // 4096 float4s
            int r = idx >> 5, c = idx & 31;
            float4 val = qg[r * 32 + c];
            float* dst = &Qs[r * QPAD + c * 4];
            dst[0] = to_tf32(val.x); dst[1] = to_tf32(val.y);
            dst[2] = to_tf32(val.z); dst[3] = to_tf32(val.w);
        }
    }

    float oacc[4][4][4];
    #pragma unroll
    for (int a = 0; a < 4; a++)
        #pragma unroll
        for (int b = 0; b < 4; b++)
            #pragma unroll
            for (int cc = 0; cc < 4; cc++) oacc[a][b][cc] = 0.f;

    for (int kt = 0; kt < SEQ; kt += TK) {
        __syncthreads();  // all warps done with previous Ks/Vs/Ss reads

        // ---- load K,V tiles [TK x DH], tf32-converted ----
        {
            const float4* kg = (const float4*)(k + base + (size_t)kt * DH);
            const float4* vg = (const float4*)(v + base + (size_t)kt * DH);
            #pragma unroll
            for (int i = 0; i < 8; i++) {
                int idx = tid + i * 256;      // 2048 float4s each
                int r = idx >> 5, c = idx & 31;
                float4 kv = kg[r * 32 + c];
                float* dk = &Ks[r * QPAD + c * 4];
                dk[0] = to_tf32(kv.x); dk[1] = to_tf32(kv.y);
                dk[2] = to_tf32(kv.z); dk[3] = to_tf32(kv.w);
                float4 vv = vg[r * 32 + c];
                float* dv = &Vs[r * QPAD + c * 4];
                dv[0] = to_tf32(vv.x); dv[1] = to_tf32(vv.y);
                dv[2] = to_tf32(vv.z); dv[3] = to_tf32(vv.w);
            }
        }
        __syncthreads();

        // ---- GEMM1: S = Q @ K^T  (k-dim = DH) ----
        float sacc[4][2][4];
        #pragma unroll
        for (int a = 0; a < 4; a++)
            #pragma unroll
            for (int b = 0; b < 2; b++)
                #pragma unroll
                for (int cc = 0; cc < 4; cc++) sacc[a][b][cc] = 0.f;

        #pragma unroll
        for (int k0 = 0; k0 < DH; k0 += 8) {
            u32 bf[2][2];
            #pragma unroll
            for (int ni = 0; ni < 2; ni++) {
                const float2 bb = *(const float2*)&Ks[(wn * 16 + ni * 8 + g) * QPAD + k0 + 2 * t];
                bf[ni][0] = __float_as_uint(bb.x);
                bf[ni][1] = __float_as_uint(bb.y);
            }
            #pragma unroll
            for (int mi = 0; mi < 4; mi++) {
                int rm = wm * 64 + mi * 16 + g;
                float2 aa0 = *(const float2*)&Qs[rm * QPAD + k0 + 2 * t];
                float2 aa1 = *(const float2*)&Qs[(rm + 8) * QPAD + k0 + 2 * t];
                u32 a0 = __float_as_uint(aa0.x), a2 = __float_as_uint(aa0.y);
                u32 a1 = __float_as_uint(aa1.x), a3 = __float_as_uint(aa1.y);
                mma8(sacc[mi][0], a0, a1, a2, a3, bf[0][0], bf[0][1]);
                mma8(sacc[mi][1], a0, a1, a2, a3, bf[1][0], bf[1][1]);
            }
        }

        // ---- epilogue1: relu(s*scale)^2 -> tf32 -> Ss ----
        #pragma unroll
        for (int mi = 0; mi < 4; mi++) {
            #pragma unroll
            for (int ni = 0; ni < 2; ni++) {
                int row = wm * 64 + mi * 16 + g;
                int col = wn * 16 + ni * 8 + 2 * t;
                float e[4];
                #pragma unroll
                for (int j = 0; j < 4; j++) {
                    float x = sacc[mi][ni][j] * scale;
                    x = fmaxf(x, 0.f);
                    e[j] = to_tf32(x * x);
                }
                *(float2*)&Ss[row * SPAD + col]       = make_float2(e[0], e[1]);
                *(float2*)&Ss[(row + 8) * SPAD + col] = make_float2(e[2], e[3]);
            }
        }
        __syncthreads();

        // ---- GEMM2: O += S @ V  (k-dim = TK) ----
        #pragma unroll
        for (int k0 = 0; k0 < TK; k0 += 8) {
            u32 bf2[4][2];
            #pragma unroll
            for (int ni = 0; ni < 4; ni++) {
                int cn = wn * 32 + ni * 8 + g;
                bf2[ni][0] = __float_as_uint(Vs[(k0 + 2 * t) * QPAD + cn]);
                bf2[ni][1] = __float_as_uint(Vs[(k0 + 2 * t + 1) * QPAD + cn]);
            }
            #pragma unroll
            for (int mi = 0; mi < 4; mi++) {
                int rm = wm * 64 + mi * 16 + g;
                float2 aa0 = *(const float2*)&Ss[rm * SPAD + k0 + 2 * t];
                float2 aa1 = *(const float2*)&Ss[(rm + 8) * SPAD + k0 + 2 * t];
                u32 a0 = __float_as_uint(aa0.x), a2 = __float_as_uint(aa0.y);
                u32 a1 = __float_as_uint(aa1.x), a3 = __float_as_uint(aa1.y);
                #pragma unroll
                for (int ni = 0; ni < 4; ni++)
                    mma8(oacc[mi][ni], a0, a1, a2, a3, bf2[ni][0], bf2[ni][1]);
            }
        }
    }

    // ---- write O ----
    float* og = out + base + (size_t)q0 * DH;
    #pragma unroll
    for (int mi = 0; mi < 4; mi++) {
        #pragma unroll
        for (int ni = 0; ni < 4; ni++) {
            int row = wm * 64 + mi * 16 + g;
            int col = wn * 32 + ni * 8 + 2 * t;
            *(float2*)&og[row * DH + col] =
                make_float2(oacc[mi][ni][0], oacc[mi][ni][1]);
            *(float2*)&og[(row + 8) * DH + col] =
                make_float2(oacc[mi][ni][2], oacc[mi][ni][3]);
        }
    }
}

extern "C" void kernel_launch(void* const* d_in, const int* in_sizes, int n_in,
                              void* d_out, int out_size) {
    const float* q  = (const float*)d_in[0];
    const float* k  = (const float*)d_in[1];
    const float* v  = (const float*)d_in[2];
    const float* sc = (const float*)d_in[3];
    float* out = (float*)d_out;

    const int smem_bytes = (BM * QPAD + TK * QPAD + TK * QPAD + BM * SPAD) * 4; // 169984
    cudaFuncSetAttribute(attn_relu2_kernel,
                         cudaFuncAttributeMaxDynamicSharedMemorySize, smem_bytes);

    dim3 grid(SEQ / BM, BH);
    attn_relu2_kernel<<<grid, 256, smem_bytes>>>(q, k, v, sc, out);
}

// round 5
// speedup vs baseline: 1.4477x; 1.4477x over previous
#include <cuda_runtime.h>
#include <cstdint>

#define BH   32
#define SEQ  2048
#define DH   128
#define BM   128
#define TK   64
#define NT   (SEQ / TK)
#define N_ELEM (2 * 16 * 2048 * 128)   // elements per tensor

typedef uint32_t u32;

// ---- SMEM byte offsets ----
#define SQ     0                      // Q: 128 rows x 512B        = 65536
#define SKOFF(b) (65536 + (b) * 32768)   // K: 2 x (64 x 512B)
#define SVOFF(b) (131072 + (b) * 32768)  // V: 2 x (64 x 512B)
#define SS     196608                 // S: 128 rows x 256B        = 32768
#define SMEM_TOTAL 229376

__device__ float g_scr[3 * N_ELEM];   // tf32-rounded Q,K,V scratch (bss)

__device__ __forceinline__ float to_tf32(float x) {
    u32 u;
    asm("cvt.rna.tf32.f32 %0, %1;" : "=r"(u) : "f"(x));
    return __uint_as_float(u);
}

__device__ __forceinline__ void mma8(float* c,
                                     u32 a0, u32 a1, u32 a2, u32 a3,
                                     u32 b0, u32 b1) {
    asm volatile(
        "mma.sync.aligned.m16n8k8.row.col.f32.tf32.tf32.f32 "
        "{%0,%1,%2,%3},{%4,%5,%6,%7},{%8,%9},{%0,%1,%2,%3};\n"
        : "+f"(c[0]), "+f"(c[1]), "+f"(c[2]), "+f"(c[3])
        : "r"(a0), "r"(a1), "r"(a2), "r"(a3), "r"(b0), "r"(b1));
}
#define FU __float_as_uint

#define CP16(dst, src) \
    asm volatile("cp.async.cg.shared.global [%0], [%1], 16;" :: "r"(dst), "l"(src))
#define CP_COMMIT() asm volatile("cp.async.commit_group;" ::: "memory")
#define CP_WAIT(n)  asm volatile("cp.async.wait_group %0;" :: "n"(n) : "memory")

// position of logical in-chunk column lc (0..15) in the permuted S/V order
// [0,1,8,9, 2,3,10,11, 4,5,12,13, 6,7,14,15]
__device__ __forceinline__ int posf(int lc) {
    return ((lc & 6) << 1) | ((lc >> 2) & 2) | (lc & 1);
}

// ---------------- pre-pass: round Q,K,V to tf32 into scratch ----------------
__global__ void __launch_bounds__(256)
prepass_kernel(const float* __restrict__ q, const float* __restrict__ k,
               const float* __restrict__ v) {
    const int n4 = N_ELEM / 4;
    float4* dq = (float4*)g_scr;
    float4* dk = (float4*)(g_scr + N_ELEM);
    float4* dv = (float4*)(g_scr + 2 * N_ELEM);
    for (int i = blockIdx.x * blockDim.x + threadIdx.x; i < n4;
         i += gridDim.x * blockDim.x) {
        float4 a = ((const float4*)q)[i];
        a.x = to_tf32(a.x); a.y = to_tf32(a.y); a.z = to_tf32(a.z); a.w = to_tf32(a.w);
        dq[i] = a;
        float4 b = ((const float4*)k)[i];
        b.x = to_tf32(b.x); b.y = to_tf32(b.y); b.z = to_tf32(b.z); b.w = to_tf32(b.w);
        dk[i] = b;
        float4 c = ((const float4*)v)[i];
        c.x = to_tf32(c.x); c.y = to_tf32(c.y); c.z = to_tf32(c.z); c.w = to_tf32(c.w);
        dv[i] = c;
    }
}

// ---------------- cp.async tile loaders ----------------
// K-major tile (Q/K): row r (512B), chunk c4 (16B): granule swizzle c4 ^ ((r&1)<<2)
__device__ __forceinline__ void cp_kmaj(u32 smbase, const float* __restrict__ g,
                                        int rows, int tid) {
    const int n = rows * 32;
    for (int idx = tid; idx < n; idx += 256) {
        int r = idx >> 5, c4 = idx & 31;
        u32 dst = smbase + r * 512 + ((c4 ^ ((r & 1) << 2)) << 4);
        CP16(dst, g + r * DH + c4 * 4);
    }
}
// V tile: logical row rl -> stored row R = perm; word swizzle ^(((R>>2)&3)<<3)
__device__ __forceinline__ void cp_vtile(u32 smbase, const float* __restrict__ g,
                                         int tid) {
    for (int idx = tid; idx < 64 * 32; idx += 256) {
        int rl = idx >> 5, c4 = idx & 31;
        int R = (rl & ~15) | posf(rl & 15);
        int tt = (R >> 2) & 3;
        u32 dst = smbase + R * 512 + ((c4 ^ (tt << 1)) << 4);
        CP16(dst, g + rl * DH + c4 * 4);
    }
}

// ---------------- main fused kernel ----------------
__global__ void __launch_bounds__(256, 1)
attn_relu2_kernel(const float* __restrict__ scale_p, float* __restrict__ out) {
    extern __shared__ char smp[];
    u32 sb;
    asm("{ .reg .u64 t; cvta.to.shared.u64 t, %1; cvt.u32.u64 %0, t; }"
        : "=r"(sb) : "l"(smp));

    const int tid  = threadIdx.x;
    const int lane = tid & 31;
    const int warp = tid >> 5;
    const int g = lane >> 2;        // 0..7
    const int t = lane & 3;         // 0..3
    const int wm = warp & 3;        // 4 m-strips of 32 rows
    const int wn = warp >> 2;       // 2 n-halves

    const int bh = blockIdx.y;
    const int q0 = blockIdx.x * BM;
    const float scale = *scale_p;
    const size_t base = (size_t)bh * SEQ * DH;

    const float* qs = g_scr + base + (size_t)q0 * DH;
    const float* ks = g_scr + N_ELEM + base;
    const float* vs = g_scr + 2 * N_ELEM + base;

    const int axor = (g & 1) << 2;
    int narr[8];
    #pragma unroll
    for (int ni = 0; ni < 8; ni++)
        narr[ni] = (wn * 64 + ni * 8 + g) ^ (t << 3);

    // ---- prologue: Q + KV tile 0 ----
    cp_kmaj(sb + SQ, qs, 128, tid);
    cp_kmaj(sb + SKOFF(0), ks, 64, tid);
    cp_vtile(sb + SVOFF(0), vs, tid);
    CP_COMMIT();

    float oacc[2][8][4];
    #pragma unroll
    for (int a = 0; a < 2; a++)
        #pragma unroll
        for (int b = 0; b < 8; b++)
            #pragma unroll
            for (int c = 0; c < 4; c++) oacc[a][b][c] = 0.f;

    for (int i = 0; i < NT; i++) {
        const int b = i & 1;
        __syncthreads();   // retire GEMM2(i-1): buf b^1 and S free

        if (i + 1 < NT) {
            cp_kmaj(sb + SKOFF(b ^ 1), ks + (size_t)(i + 1) * TK * DH, 64, tid);
            cp_vtile(sb + SVOFF(b ^ 1), vs + (size_t)(i + 1) * TK * DH, tid);
            CP_COMMIT();
            CP_WAIT(1);    // tile i arrived (i+1 may be in flight)
        } else {
            CP_WAIT(0);
        }
        __syncthreads();   // tile i visible to all warps

        // ---- GEMM1: S[128x64] = Q @ K^T ----
        float sacc[2][4][4];
        #pragma unroll
        for (int a = 0; a < 2; a++)
            #pragma unroll
            for (int bb = 0; bb < 4; bb++)
                #pragma unroll
                for (int c = 0; c < 4; c++) sacc[a][bb][c] = 0.f;

        const u32 Kb = sb + SKOFF(b);
        #pragma unroll
        for (int kc = 0; kc < 8; kc++) {
            const int gsel = ((kc * 4 + t) ^ axor) << 4;
            float4 Bf[4];
            #pragma unroll
            for (int ni = 0; ni < 4; ni++) {
                int rb = wn * 32 + ni * 8 + g;
                Bf[ni] = *(const float4*)(smp + (SKOFF(b) + rb * 512) + gsel);
            }
            float4 Af[2][2];
            #pragma unroll
            for (int mi = 0; mi < 2; mi++) {
                int r0 = wm * 32 + mi * 16 + g;
                Af[mi][0] = *(const float4*)(smp + SQ + r0 * 512 + gsel);
                Af[mi][1] = *(const float4*)(smp + SQ + (r0 + 8) * 512 + gsel);
            }
            #pragma unroll
            for (int mi = 0; mi < 2; mi++)
                #pragma unroll
                for (int ni = 0; ni < 4; ni++) {
                    mma8(sacc[mi][ni],
                         FU(Af[mi][0].x), FU(Af[mi][1].x),
                         FU(Af[mi][0].y), FU(Af[mi][1].y),
                         FU(Bf[ni].x), FU(Bf[ni].y));
                    mma8(sacc[mi][ni],
                         FU(Af[mi][0].z), FU(Af[mi][1].z),
                         FU(Af[mi][0].w), FU(Af[mi][1].w),
                         FU(Bf[ni].z), FU(Bf[ni].w));
                }
        }

        // ---- epilogue: relu(s*scale)^2 -> tf32 -> S smem (permuted+swizzled) ----
        #pragma unroll
        for (int mi = 0; mi < 2; mi++) {
            #pragma unroll
            for (int ni = 0; ni < 4; ni++) {
                const int kc1 = wn * 2 + (ni >> 1);
                const int offb = (ni & 1) * 8;
                const int gsel = (((kc1 * 4 + t) ^ axor) << 4) + offb;
                float e[4];
                #pragma unroll
                for (int j = 0; j < 4; j++) {
                    float x = fmaxf(sacc[mi][ni][j] * scale, 0.f);
                    e[j] = to_tf32(x * x);
                }
                int r0 = wm * 32 + mi * 16 + g;
                *(float2*)(smp + SS + r0 * 256 + gsel) = make_float2(e[0], e[1]);
                *(float2*)(smp + SS + (r0 + 8) * 256 + gsel) = make_float2(e[2], e[3]);
            }
        }
        __syncthreads();   // S visible

        // ---- GEMM2: O += S @ V ----
        #pragma unroll
        for (int kc = 0; kc < 4; kc++) {
            const int gsel = ((kc * 4 + t) ^ axor) << 4;
            float4 As[2][2];
            #pragma unroll
            for (int mi = 0; mi < 2; mi++) {
                int r0 = wm * 32 + mi * 16 + g;
                As[mi][0] = *(const float4*)(smp + SS + r0 * 256 + gsel);
                As[mi][1] = *(const float4*)(smp + SS + (r0 + 8) * 256 + gsel);
            }
            const int Rb = kc * 16 + 4 * t;
            #pragma unroll
            for (int h = 0; h < 2; h++) {
                float bf[4][4];
                #pragma unroll
                for (int nj = 0; nj < 4; nj++) {
                    const int nw = narr[h * 4 + nj];
                    #pragma unroll
                    for (int j = 0; j < 4; j++)
                        bf[nj][j] = *(const float*)(smp + SVOFF(b) +
                                                    (Rb + j) * 512 + nw * 4);
                }
                #pragma unroll
                for (int mi = 0; mi < 2; mi++)
                    #pragma unroll
                    for (int nj = 0; nj < 4; nj++) {
                        mma8(oacc[mi][h * 4 + nj],
                             FU(As[mi][0].x), FU(As[mi][1].x),
                             FU(As[mi][0].y), FU(As[mi][1].y),
                             FU(bf[nj][0]), FU(bf[nj][1]));
                        mma8(oacc[mi][h * 4 + nj],
                             FU(As[mi][0].z), FU(As[mi][1].z),
                             FU(As[mi][0].w), FU(As[mi][1].w),
                             FU(bf[nj][2]), FU(bf[nj][3]));
                    }
            }
        }
    }

    // ---- write O ----
    float* og = out + base + (size_t)q0 * DH;
    #pragma unroll
    for (int mi = 0; mi < 2; mi++) {
        #pragma unroll
        for (int ni = 0; ni < 8; ni++) {
            int r0 = wm * 32 + mi * 16 + g;
            int col = wn * 64 + ni * 8 + 2 * t;
            *(float2*)(og + (size_t)r0 * DH + col) =
                make_float2(oacc[mi][ni][0], oacc[mi][ni][1]);
            *(float2*)(og + (size_t)(r0 + 8) * DH + col) =
                make_float2(oacc[mi][ni][2], oacc[mi][ni][3]);
        }
    }
}

extern "C" void kernel_launch(void* const* d_in, const int* in_sizes, int n_in,
                              void* d_out, int out_size) {
    const float* q  = (const float*)d_in[0];
    const float* k  = (const float*)d_in[1];
    const float* v  = (const float*)d_in[2];
    const float* sc = (const float*)d_in[3];
    float* out = (float*)d_out;

    prepass_kernel<<<1024, 256>>>(q, k, v);

    cudaFuncSetAttribute(attn_relu2_kernel,
                         cudaFuncAttributeMaxDynamicSharedMemorySize, SMEM_TOTAL);
    dim3 grid(SEQ / BM, BH);
    attn_relu2_kernel<<<grid, 256, SMEM_TOTAL>>>(sc, out);
}